// round 8
// baseline (speedup 1.0000x reference)
#include <cuda_runtime.h>

#define B_DIM 256
#define M_DIM 4096
#define HALF_M 2048
#define BLK 256
#define ROW_CHUNKS 512               /* 2 chunks per row */
#define RECON_BLOCKS 188
#define GRID_B (ROW_CHUNKS + RECON_BLOCKS)
#define RECON_N4 (256 * 128 * 128 / 4)
#define EPSF 1e-7f

// Per-block partials: [coord, width, n_valid, bce(log2), cont, recon_sq]
__device__ float  g_part[GRID_B * 6];
__device__ float2 g_edge_first[ROW_CHUNKS];
__device__ float2 g_edge_last[ROW_CHUNKS];
__device__ int    g_edge_cnt[ROW_CHUNKS];
__device__ unsigned int g_count = 0;   // reset to 0 by the last block each launch

__global__ void __launch_bounds__(BLK) fused_kernel(
    const float* __restrict__ pred,
    const float* __restrict__ tgt,
    const float* __restrict__ rec,
    const float* __restrict__ img,
    float* __restrict__ out)
{
    __shared__ float2        s_p45[HALF_M];   // 16 KB
    __shared__ float2        s_comp[HALF_M];  // 16 KB
    __shared__ unsigned char s_mask[HALF_M];  // 2 KB
    __shared__ int    s_wsum[BLK / 32];
    __shared__ float  s_red[BLK / 32];
    __shared__ int    s_total;
    __shared__ unsigned int s_is_last;
    __shared__ double s_dred[BLK / 32][6];

    const int tid = threadIdx.x;
    const int bid = blockIdx.x;

    if (bid < ROW_CHUNKS) {
        // ----------------- Row-chunk blocks: half a batch row each -----------------
        const int row  = bid >> 1;
        const int half = bid & 1;
        const size_t base = ((size_t)row * M_DIM + (size_t)half * HALF_M) * 9;
        const float4* p4 = (const float4*)(pred + base);
        const float4* t4 = (const float4*)(tgt  + base);

        float coord = 0.f, width = 0.f, bce = 0.f;

        // Single coalesced pass. Superblock = 4 positions = 9 float4 per array.
        for (int s = tid; s < HALF_M / 4; s += BLK) {
            float cs = 0.f, ws = 0.f, sp4 = 0.f, sp5 = 0.f;
            #pragma unroll
            for (int k = 0; k < 9; k++) {
                float4 pv = __ldg(p4 + s * 9 + k);
                float4 tv = __ldg(t4 + s * 9 + k);
                float pa[4] = {pv.x, pv.y, pv.z, pv.w};
                float ta[4] = {tv.x, tv.y, tv.z, tv.w};
                #pragma unroll
                for (int l = 0; l < 4; l++) {
                    const int e = 4 * k + l;      // 0..35
                    const int q = e / 9;          // position within superblock
                    const int c = e % 9;          // channel (compile-time)
                    float pd = pa[l], td = ta[l];
                    if (c < 4) {
                        cs += fabsf(pd - td);
                    } else if (c == 4) {
                        cs += fabsf(pd - td); sp4 = pd;
                    } else if (c == 5) {
                        cs += fabsf(pd - td); sp5 = pd;
                    } else if (c < 8) {
                        ws += fabsf(pd - td);
                    } else {                       // c == 8: finish position q
                        const int pos = s * 4 + q;
                        int m = (td > 0.5f) ? 1 : 0;
                        s_mask[pos] = (unsigned char)m;
                        s_p45[pos]  = make_float2(sp4, sp5);
                        float fm = (float)m;
                        coord = fmaf(cs, fm, coord);
                        width = fmaf(ws, fm, width);
                        float pc = fminf(fmaxf(pd, EPSF), 1.f - EPSF);
                        bce -= td * __log2f(pc) + (1.f - td) * __log2f(1.f - pc);
                        cs = 0.f; ws = 0.f;
                    }
                }
            }
        }
        __syncthreads();

        // Scan masks (8 contiguous positions per thread) -> compaction in SMEM.
        const int pbase = tid * 8;
        int cnt = 0;
        #pragma unroll
        for (int j = 0; j < 8; j++) cnt += (int)s_mask[pbase + j];
        const int lane = tid & 31, wrp = tid >> 5;
        int inc = cnt;
        #pragma unroll
        for (int o = 1; o < 32; o <<= 1) {
            int v = __shfl_up_sync(0xFFFFFFFFu, inc, o);
            if (lane >= o) inc += v;
        }
        if (lane == 31) s_wsum[wrp] = inc;
        __syncthreads();
        int wbase = 0;
        for (int w = 0; w < wrp; w++) wbase += s_wsum[w];
        int r = wbase + inc - cnt;                 // exclusive prefix
        #pragma unroll
        for (int j = 0; j < 8; j++) {
            if (s_mask[pbase + j]) { s_comp[r] = s_p45[pbase + j]; r++; }
        }
        if (tid == BLK - 1) s_total = r;
        __syncthreads();

        const int total = s_total;
        if (tid == 0) {
            g_edge_cnt[bid] = total;
            if (total > 0) {
                g_edge_first[bid] = s_comp[0];
                g_edge_last[bid]  = s_comp[total - 1];
            } else {
                g_edge_first[bid] = make_float2(0.f, 0.f);
                g_edge_last[bid]  = make_float2(0.f, 0.f);
            }
        }

        // Continuity: adjacent compacted valid pairs within this chunk.
        float cont = 0.f;
        for (int j = tid; j + 1 < total; j += BLK) {
            float2 a = s_comp[j], c = s_comp[j + 1];
            cont += fabsf(a.x - c.x) + fabsf(a.y - c.y);
        }
        cont *= 0.5f;

        // Block-reduce 4 floats, write partials.
        float vals[4] = {coord, width, bce, cont};
        float red[4];
        #pragma unroll
        for (int v = 0; v < 4; v++) {
            float a = vals[v];
            #pragma unroll
            for (int o = 16; o; o >>= 1) a += __shfl_down_sync(0xFFFFFFFFu, a, o);
            if (lane == 0) s_red[wrp] = a;
            __syncthreads();
            if (tid == 0) {
                float ssum = 0.f;
                #pragma unroll
                for (int w = 0; w < BLK / 32; w++) ssum += s_red[w];
                red[v] = ssum;
            }
            __syncthreads();
        }
        if (tid == 0) {
            g_part[bid * 6 + 0] = red[0];
            g_part[bid * 6 + 1] = red[1];
            g_part[bid * 6 + 2] = (float)total;
            g_part[bid * 6 + 3] = red[2];
            g_part[bid * 6 + 4] = red[3];
            g_part[bid * 6 + 5] = 0.f;
        }
    } else {
        // ----------------- Recon-MSE blocks -----------------
        const int rb = bid - ROW_CHUNKS;
        const float4* r4 = (const float4*)rec;
        const float4* i4 = (const float4*)img;
        float acc = 0.f;
        for (int i = rb * BLK + tid; i < RECON_N4; i += RECON_BLOCKS * BLK) {
            float4 a = __ldg(r4 + i);
            float4 b = __ldg(i4 + i);
            float d0 = a.x - b.x, d1 = a.y - b.y, d2 = a.z - b.z, d3 = a.w - b.w;
            acc = fmaf(d0, d0, acc);
            acc = fmaf(d1, d1, acc);
            acc = fmaf(d2, d2, acc);
            acc = fmaf(d3, d3, acc);
        }
        const int lane = tid & 31, wrp = tid >> 5;
        #pragma unroll
        for (int o = 16; o; o >>= 1) acc += __shfl_down_sync(0xFFFFFFFFu, acc, o);
        if (lane == 0) s_red[wrp] = acc;
        __syncthreads();
        if (tid == 0) {
            float s = 0.f;
            #pragma unroll
            for (int w = 0; w < BLK / 32; w++) s += s_red[w];
            g_part[bid * 6 + 0] = 0.f;
            g_part[bid * 6 + 1] = 0.f;
            g_part[bid * 6 + 2] = 0.f;
            g_part[bid * 6 + 3] = 0.f;
            g_part[bid * 6 + 4] = 0.f;
            g_part[bid * 6 + 5] = s;
        }
    }

    // ----------------- Last-block finalize -----------------
    __threadfence();
    if (tid == 0) s_is_last = (atomicAdd(&g_count, 1u) == GRID_B - 1);
    __syncthreads();
    if (!s_is_last) return;

    double a0 = 0, a1 = 0, a2 = 0, a3 = 0, a4 = 0, a5 = 0;
    for (int i = tid; i < GRID_B; i += BLK) {
        a0 += (double)g_part[i * 6 + 0];
        a1 += (double)g_part[i * 6 + 1];
        a2 += (double)g_part[i * 6 + 2];
        a3 += (double)g_part[i * 6 + 3];
        a4 += (double)g_part[i * 6 + 4];
        a5 += (double)g_part[i * 6 + 5];
    }
    // Cross-chunk continuity boundaries (one per row; 2 chunks/row).
    for (int rw = tid; rw < B_DIM; rw += BLK) {
        int c0 = 2 * rw, c1 = 2 * rw + 1;
        if (g_edge_cnt[c0] > 0 && g_edge_cnt[c1] > 0) {
            float2 L = g_edge_last[c0], F = g_edge_first[c1];
            a4 += 0.5 * ((double)fabsf(L.x - F.x) + (double)fabsf(L.y - F.y));
        }
    }
    // Reduce 6 doubles across the block.
    const int lane = tid & 31, wrp = tid >> 5;
    double accs[6] = {a0, a1, a2, a3, a4, a5};
    #pragma unroll
    for (int v = 0; v < 6; v++) {
        double a = accs[v];
        #pragma unroll
        for (int o = 16; o; o >>= 1) a += __shfl_down_sync(0xFFFFFFFFu, a, o);
        if (lane == 0) s_dred[wrp][v] = a;
    }
    __syncthreads();
    if (tid == 0) {
        double f[6] = {0, 0, 0, 0, 0, 0};
        #pragma unroll
        for (int w = 0; w < BLK / 32; w++)
            #pragma unroll
            for (int v = 0; v < 6; v++) f[v] += s_dred[w][v];
        double nv = f[2];
        double coord = 0.0, width = 0.0;
        if (nv > 0.0) {
            coord = f[0] / fmax(nv * 6.0, 1.0);
            width = f[1] / fmax(nv * 2.0, 1.0);
        }
        double bce  = f[3] * 0.6931471805599453 / ((double)B_DIM * (double)M_DIM);
        double cont = f[4] / (double)B_DIM;
        double rcn  = f[5] / ((double)B_DIM * 128.0 * 128.0);
        out[0] = (float)(coord + width + 2.0 * bce + 0.2 * cont + 0.1 * rcn);
        g_count = 0;   // reset for next graph replay
    }
}

extern "C" void kernel_launch(void* const* d_in, const int* in_sizes, int n_in,
                              void* d_out, int out_size) {
    const float* pred = (const float*)d_in[0];
    const float* tgt  = (const float*)d_in[1];
    const float* rec  = (const float*)d_in[2];
    const float* img  = (const float*)d_in[3];
    fused_kernel<<<GRID_B, BLK>>>(pred, tgt, rec, img, (float*)d_out);
}

// round 12
// speedup vs baseline: 1.0353x; 1.0353x over previous
#include <cuda_runtime.h>

#define B_DIM 256
#define M_DIM 4096
#define HALF_M 2048
#define BLK 256
#define ROW_CHUNKS 512               /* 2 chunks per row */
#define RECON_BLOCKS 188
#define GRID_B (ROW_CHUNKS + RECON_BLOCKS)
#define RECON_N4 (256 * 128 * 128 / 4)
#define EPSF 1e-7f

// Per-block partials: [coord, width, n_valid, bce(log2), cont, recon_sq]
__device__ float  g_part[GRID_B * 6];
__device__ float2 g_edge_first[ROW_CHUNKS];
__device__ float2 g_edge_last[ROW_CHUNKS];
__device__ int    g_edge_cnt[ROW_CHUNKS];
__device__ unsigned int g_count = 0;   // reset to 0 by the last block each launch

__global__ void __launch_bounds__(BLK) fused_kernel(
    const float* __restrict__ pred,
    const float* __restrict__ tgt,
    const float* __restrict__ rec,
    const float* __restrict__ img,
    float* __restrict__ out)
{
    __shared__ float2        s_p45[HALF_M];   // 16 KB
    __shared__ float2        s_comp[HALF_M];  // 16 KB
    __shared__ unsigned char s_mask[HALF_M];  // 2 KB
    __shared__ int    s_wsum[BLK / 32];
    __shared__ float  s_red[BLK / 32];
    __shared__ int    s_total;
    __shared__ unsigned int s_is_last;
    __shared__ double s_dred[BLK / 32][6];

    const int tid = threadIdx.x;
    const int bid = blockIdx.x;

    if (bid < ROW_CHUNKS) {
        // ----------------- Row-chunk blocks: half a batch row each -----------------
        const int row  = bid >> 1;
        const int half = bid & 1;
        const size_t base = ((size_t)row * M_DIM + (size_t)half * HALF_M) * 9;
        const float4* p4 = (const float4*)(pred + base);
        const float4* t4 = (const float4*)(tgt  + base);

        float coord = 0.f, width = 0.f, bce = 0.f;

        // Single coalesced pass. Superblock = 4 positions = 9 float4 per array.
        for (int s = tid; s < HALF_M / 4; s += BLK) {
            float cs = 0.f, ws = 0.f, sp4 = 0.f, sp5 = 0.f;
            #pragma unroll
            for (int k = 0; k < 9; k++) {
                float4 pv = __ldg(p4 + s * 9 + k);
                float4 tv = __ldg(t4 + s * 9 + k);
                float pa[4] = {pv.x, pv.y, pv.z, pv.w};
                float ta[4] = {tv.x, tv.y, tv.z, tv.w};
                #pragma unroll
                for (int l = 0; l < 4; l++) {
                    const int e = 4 * k + l;      // 0..35
                    const int q = e / 9;          // position within superblock
                    const int c = e % 9;          // channel (compile-time)
                    float pd = pa[l], td = ta[l];
                    if (c < 4) {
                        cs += fabsf(pd - td);
                    } else if (c == 4) {
                        cs += fabsf(pd - td); sp4 = pd;
                    } else if (c == 5) {
                        cs += fabsf(pd - td); sp5 = pd;
                    } else if (c < 8) {
                        ws += fabsf(pd - td);
                    } else {                       // c == 8: finish position q
                        const int pos = s * 4 + q;
                        int m = (td > 0.5f) ? 1 : 0;
                        s_mask[pos] = (unsigned char)m;
                        s_p45[pos]  = make_float2(sp4, sp5);
                        float fm = (float)m;
                        coord = fmaf(cs, fm, coord);
                        width = fmaf(ws, fm, width);
                        float pc = fminf(fmaxf(pd, EPSF), 1.f - EPSF);
                        bce -= td * __log2f(pc) + (1.f - td) * __log2f(1.f - pc);
                        cs = 0.f; ws = 0.f;
                    }
                }
            }
        }
        __syncthreads();

        // Scan masks (8 contiguous positions per thread) -> compaction in SMEM.
        const int pbase = tid * 8;
        int cnt = 0;
        #pragma unroll
        for (int j = 0; j < 8; j++) cnt += (int)s_mask[pbase + j];
        const int lane = tid & 31, wrp = tid >> 5;
        int inc = cnt;
        #pragma unroll
        for (int o = 1; o < 32; o <<= 1) {
            int v = __shfl_up_sync(0xFFFFFFFFu, inc, o);
            if (lane >= o) inc += v;
        }
        if (lane == 31) s_wsum[wrp] = inc;
        __syncthreads();
        int wbase = 0;
        for (int w = 0; w < wrp; w++) wbase += s_wsum[w];
        int r = wbase + inc - cnt;                 // exclusive prefix
        #pragma unroll
        for (int j = 0; j < 8; j++) {
            if (s_mask[pbase + j]) { s_comp[r] = s_p45[pbase + j]; r++; }
        }
        if (tid == BLK - 1) s_total = r;
        __syncthreads();

        const int total = s_total;
        if (tid == 0) {
            g_edge_cnt[bid] = total;
            if (total > 0) {
                g_edge_first[bid] = s_comp[0];
                g_edge_last[bid]  = s_comp[total - 1];
            } else {
                g_edge_first[bid] = make_float2(0.f, 0.f);
                g_edge_last[bid]  = make_float2(0.f, 0.f);
            }
        }

        // Continuity: adjacent compacted valid pairs within this chunk.
        float cont = 0.f;
        for (int j = tid; j + 1 < total; j += BLK) {
            float2 a = s_comp[j], c = s_comp[j + 1];
            cont += fabsf(a.x - c.x) + fabsf(a.y - c.y);
        }
        cont *= 0.5f;

        // Block-reduce 4 floats, write partials.
        float vals[4] = {coord, width, bce, cont};
        float red[4];
        #pragma unroll
        for (int v = 0; v < 4; v++) {
            float a = vals[v];
            #pragma unroll
            for (int o = 16; o; o >>= 1) a += __shfl_down_sync(0xFFFFFFFFu, a, o);
            if (lane == 0) s_red[wrp] = a;
            __syncthreads();
            if (tid == 0) {
                float ssum = 0.f;
                #pragma unroll
                for (int w = 0; w < BLK / 32; w++) ssum += s_red[w];
                red[v] = ssum;
            }
            __syncthreads();
        }
        if (tid == 0) {
            g_part[bid * 6 + 0] = red[0];
            g_part[bid * 6 + 1] = red[1];
            g_part[bid * 6 + 2] = (float)total;
            g_part[bid * 6 + 3] = red[2];
            g_part[bid * 6 + 4] = red[3];
            g_part[bid * 6 + 5] = 0.f;
        }
    } else {
        // ----------------- Recon-MSE blocks -----------------
        const int rb = bid - ROW_CHUNKS;
        const float4* r4 = (const float4*)rec;
        const float4* i4 = (const float4*)img;
        float acc = 0.f;
        for (int i = rb * BLK + tid; i < RECON_N4; i += RECON_BLOCKS * BLK) {
            float4 a = __ldg(r4 + i);
            float4 b = __ldg(i4 + i);
            float d0 = a.x - b.x, d1 = a.y - b.y, d2 = a.z - b.z, d3 = a.w - b.w;
            acc = fmaf(d0, d0, acc);
            acc = fmaf(d1, d1, acc);
            acc = fmaf(d2, d2, acc);
            acc = fmaf(d3, d3, acc);
        }
        const int lane = tid & 31, wrp = tid >> 5;
        #pragma unroll
        for (int o = 16; o; o >>= 1) acc += __shfl_down_sync(0xFFFFFFFFu, acc, o);
        if (lane == 0) s_red[wrp] = acc;
        __syncthreads();
        if (tid == 0) {
            float s = 0.f;
            #pragma unroll
            for (int w = 0; w < BLK / 32; w++) s += s_red[w];
            g_part[bid * 6 + 0] = 0.f;
            g_part[bid * 6 + 1] = 0.f;
            g_part[bid * 6 + 2] = 0.f;
            g_part[bid * 6 + 3] = 0.f;
            g_part[bid * 6 + 4] = 0.f;
            g_part[bid * 6 + 5] = s;
        }
    }

    // ----------------- Last-block finalize -----------------
    __threadfence();
    if (tid == 0) s_is_last = (atomicAdd(&g_count, 1u) == GRID_B - 1);
    __syncthreads();
    if (!s_is_last) return;

    double a0 = 0, a1 = 0, a2 = 0, a3 = 0, a4 = 0, a5 = 0;
    for (int i = tid; i < GRID_B; i += BLK) {
        a0 += (double)g_part[i * 6 + 0];
        a1 += (double)g_part[i * 6 + 1];
        a2 += (double)g_part[i * 6 + 2];
        a3 += (double)g_part[i * 6 + 3];
        a4 += (double)g_part[i * 6 + 4];
        a5 += (double)g_part[i * 6 + 5];
    }
    // Cross-chunk continuity boundaries (one per row; 2 chunks/row).
    for (int rw = tid; rw < B_DIM; rw += BLK) {
        int c0 = 2 * rw, c1 = 2 * rw + 1;
        if (g_edge_cnt[c0] > 0 && g_edge_cnt[c1] > 0) {
            float2 L = g_edge_last[c0], F = g_edge_first[c1];
            a4 += 0.5 * ((double)fabsf(L.x - F.x) + (double)fabsf(L.y - F.y));
        }
    }
    // Reduce 6 doubles across the block.
    const int lane = tid & 31, wrp = tid >> 5;
    double accs[6] = {a0, a1, a2, a3, a4, a5};
    #pragma unroll
    for (int v = 0; v < 6; v++) {
        double a = accs[v];
        #pragma unroll
        for (int o = 16; o; o >>= 1) a += __shfl_down_sync(0xFFFFFFFFu, a, o);
        if (lane == 0) s_dred[wrp][v] = a;
    }
    __syncthreads();
    if (tid == 0) {
        double f[6] = {0, 0, 0, 0, 0, 0};
        #pragma unroll
        for (int w = 0; w < BLK / 32; w++)
            #pragma unroll
            for (int v = 0; v < 6; v++) f[v] += s_dred[w][v];
        double nv = f[2];
        double coord = 0.0, width = 0.0;
        if (nv > 0.0) {
            coord = f[0] / fmax(nv * 6.0, 1.0);
            width = f[1] / fmax(nv * 2.0, 1.0);
        }
        double bce  = f[3] * 0.6931471805599453 / ((double)B_DIM * (double)M_DIM);
        double cont = f[4] / (double)B_DIM;
        double rcn  = f[5] / ((double)B_DIM * 128.0 * 128.0);
        out[0] = (float)(coord + width + 2.0 * bce + 0.2 * cont + 0.1 * rcn);
        g_count = 0;   // reset for next graph replay
    }
}

extern "C" void kernel_launch(void* const* d_in, const int* in_sizes, int n_in,
                              void* d_out, int out_size) {
    const float* pred = (const float*)d_in[0];
    const float* tgt  = (const float*)d_in[1];
    const float* rec  = (const float*)d_in[2];
    const float* img  = (const float*)d_in[3];
    fused_kernel<<<GRID_B, BLK>>>(pred, tgt, rec, img, (float*)d_out);
}

// round 17
// speedup vs baseline: 1.8085x; 1.7469x over previous
#include <cuda_runtime.h>

#define B_DIM 256
#define M_DIM 4096
#define HALF_M 2048
#define BLK 256
#define ROW_CHUNKS 512               /* 2 chunks per row */
#define RECON_BLOCKS 188
#define GRID_B (ROW_CHUNKS + RECON_BLOCKS)
#define RECON_N4 (256 * 128 * 128 / 4)
#define EPSF 1e-7f

// Per-block partials: [coord, width, n_valid, bce(log2), cont, recon_sq]
__device__ float  g_part[GRID_B * 6];
__device__ float2 g_edge_first[ROW_CHUNKS];
__device__ float2 g_edge_last[ROW_CHUNKS];
__device__ int    g_edge_cnt[ROW_CHUNKS];
__device__ unsigned int g_count = 0;   // reset by last block each launch

__global__ void __launch_bounds__(BLK) fused_kernel(
    const float* __restrict__ pred,
    const float* __restrict__ tgt,
    const float* __restrict__ rec,
    const float* __restrict__ img,
    float* __restrict__ out)
{
    __shared__ float2        s_p45[HALF_M];   // 16 KB (reused for compaction)
    __shared__ unsigned char s_mask[HALF_M];  // 2 KB
    __shared__ int    s_wsum[BLK / 32];
    __shared__ float  s_red[BLK / 32];
    __shared__ int    s_total;
    __shared__ unsigned int s_is_last;
    __shared__ double s_dred[BLK / 32][6];

    const int tid  = threadIdx.x;
    const int bid  = blockIdx.x;
    const int lane = tid & 31, wrp = tid >> 5;

    if (bid < ROW_CHUNKS) {
        // ------------- Row-chunk blocks: half a batch row each -------------
        const int row  = bid >> 1;
        const int half = bid & 1;
        const size_t base = ((size_t)row * M_DIM + (size_t)half * HALF_M) * 9;
        const float4* p4 = (const float4*)(pred + base);
        const float4* t4 = (const float4*)(tgt  + base);

        float coord = 0.f, width = 0.f, bce = 0.f;

        // Main sweep: superblock = 4 positions = 9 float4 per array.
        // All 18 LDG.128 front-batched into register arrays for high MLP.
        for (int s = tid; s < HALF_M / 4; s += BLK) {
            float p[36], t[36];
            #pragma unroll
            for (int k = 0; k < 9; k++) {
                float4 v = __ldg(p4 + s * 9 + k);
                p[4 * k] = v.x; p[4 * k + 1] = v.y; p[4 * k + 2] = v.z; p[4 * k + 3] = v.w;
                float4 w = __ldg(t4 + s * 9 + k);
                t[4 * k] = w.x; t[4 * k + 1] = w.y; t[4 * k + 2] = w.z; t[4 * k + 3] = w.w;
            }
            #pragma unroll
            for (int q = 0; q < 4; q++) {
                const int b = q * 9;
                const int pos = s * 4 + q;
                int m = (t[b + 8] > 0.5f) ? 1 : 0;
                float fm = (float)m;
                float cs = fabsf(p[b] - t[b]) + fabsf(p[b + 1] - t[b + 1]) +
                           fabsf(p[b + 2] - t[b + 2]) + fabsf(p[b + 3] - t[b + 3]) +
                           fabsf(p[b + 4] - t[b + 4]) + fabsf(p[b + 5] - t[b + 5]);
                coord = fmaf(cs, fm, coord);
                float ws = fabsf(p[b + 6] - t[b + 6]) + fabsf(p[b + 7] - t[b + 7]);
                width = fmaf(ws, fm, width);
                float pc = fminf(fmaxf(p[b + 8], EPSF), 1.f - EPSF);
                float tv = t[b + 8];
                bce -= tv * __log2f(pc) + (1.f - tv) * __log2f(1.f - pc);
                s_mask[pos] = (unsigned char)m;
                s_p45[pos]  = make_float2(p[b + 4], p[b + 5]);
            }
        }
        __syncthreads();

        // Compaction: pull own 8 entries to registers, scan, scatter in place.
        const int pbase = tid * 8;
        float2 myv[8];
        int mym[8];
        int cnt = 0;
        #pragma unroll
        for (int j = 0; j < 8; j++) {
            mym[j] = (int)s_mask[pbase + j];
            myv[j] = s_p45[pbase + j];
            cnt += mym[j];
        }
        int inc = cnt;
        #pragma unroll
        for (int o = 1; o < 32; o <<= 1) {
            int v = __shfl_up_sync(0xFFFFFFFFu, inc, o);
            if (lane >= o) inc += v;
        }
        if (lane == 31) s_wsum[wrp] = inc;
        __syncthreads();   // also: all s_p45 reads done before overwrite
        int wbase = 0;
        for (int w = 0; w < wrp; w++) wbase += s_wsum[w];
        int r = wbase + inc - cnt;                 // exclusive prefix
        #pragma unroll
        for (int j = 0; j < 8; j++) {
            if (mym[j]) { s_p45[r] = myv[j]; r++; }
        }
        if (tid == BLK - 1) s_total = r;
        __syncthreads();

        const int total = s_total;
        if (tid == 0) {
            g_edge_cnt[bid] = total;
            if (total > 0) {
                g_edge_first[bid] = s_p45[0];
                g_edge_last[bid]  = s_p45[total - 1];
            } else {
                g_edge_first[bid] = make_float2(0.f, 0.f);
                g_edge_last[bid]  = make_float2(0.f, 0.f);
            }
        }

        // Continuity over adjacent compacted valid pairs in this chunk.
        float cont = 0.f;
        for (int j = tid; j + 1 < total; j += BLK) {
            float2 a = s_p45[j], c = s_p45[j + 1];
            cont += fabsf(a.x - c.x) + fabsf(a.y - c.y);
        }
        cont *= 0.5f;

        // Block-reduce 4 floats -> per-block partials.
        float vals[4] = {coord, width, bce, cont};
        float red[4];
        #pragma unroll
        for (int v = 0; v < 4; v++) {
            float a = vals[v];
            #pragma unroll
            for (int o = 16; o; o >>= 1) a += __shfl_down_sync(0xFFFFFFFFu, a, o);
            if (lane == 0) s_red[wrp] = a;
            __syncthreads();
            if (tid == 0) {
                float ssum = 0.f;
                #pragma unroll
                for (int w = 0; w < BLK / 32; w++) ssum += s_red[w];
                red[v] = ssum;
            }
            __syncthreads();
        }
        if (tid == 0) {
            g_part[bid * 6 + 0] = red[0];
            g_part[bid * 6 + 1] = red[1];
            g_part[bid * 6 + 2] = (float)total;
            g_part[bid * 6 + 3] = red[2];
            g_part[bid * 6 + 4] = red[3];
            g_part[bid * 6 + 5] = 0.f;
        }
    } else {
        // ----------------- Recon-MSE blocks -----------------
        const int rb = bid - ROW_CHUNKS;
        const float4* r4 = (const float4*)rec;
        const float4* i4 = (const float4*)img;
        float acc = 0.f;
        const int stride = RECON_BLOCKS * BLK;
        #pragma unroll 4
        for (int i = rb * BLK + tid; i < RECON_N4; i += stride) {
            float4 a = __ldg(r4 + i);
            float4 b = __ldg(i4 + i);
            float d0 = a.x - b.x, d1 = a.y - b.y, d2 = a.z - b.z, d3 = a.w - b.w;
            acc = fmaf(d0, d0, acc);
            acc = fmaf(d1, d1, acc);
            acc = fmaf(d2, d2, acc);
            acc = fmaf(d3, d3, acc);
        }
        #pragma unroll
        for (int o = 16; o; o >>= 1) acc += __shfl_down_sync(0xFFFFFFFFu, acc, o);
        if (lane == 0) s_red[wrp] = acc;
        __syncthreads();
        if (tid == 0) {
            float s = 0.f;
            #pragma unroll
            for (int w = 0; w < BLK / 32; w++) s += s_red[w];
            g_part[bid * 6 + 0] = 0.f;
            g_part[bid * 6 + 1] = 0.f;
            g_part[bid * 6 + 2] = 0.f;
            g_part[bid * 6 + 3] = 0.f;
            g_part[bid * 6 + 4] = 0.f;
            g_part[bid * 6 + 5] = s;
        }
    }

    // ----------------- Last-block finalize -----------------
    __threadfence();
    if (tid == 0) s_is_last = (atomicAdd(&g_count, 1u) == GRID_B - 1);
    __syncthreads();
    if (!s_is_last) return;

    double a0 = 0, a1 = 0, a2 = 0, a3 = 0, a4 = 0, a5 = 0;
    for (int i = tid; i < GRID_B; i += BLK) {
        a0 += (double)g_part[i * 6 + 0];
        a1 += (double)g_part[i * 6 + 1];
        a2 += (double)g_part[i * 6 + 2];
        a3 += (double)g_part[i * 6 + 3];
        a4 += (double)g_part[i * 6 + 4];
        a5 += (double)g_part[i * 6 + 5];
    }
    // Cross-chunk continuity boundaries (one per row; 2 chunks/row).
    for (int rw = tid; rw < B_DIM; rw += BLK) {
        int c0 = 2 * rw, c1 = 2 * rw + 1;
        if (g_edge_cnt[c0] > 0 && g_edge_cnt[c1] > 0) {
            float2 L = g_edge_last[c0], F = g_edge_first[c1];
            a4 += 0.5 * ((double)fabsf(L.x - F.x) + (double)fabsf(L.y - F.y));
        }
    }
    double accs[6] = {a0, a1, a2, a3, a4, a5};
    #pragma unroll
    for (int v = 0; v < 6; v++) {
        double a = accs[v];
        #pragma unroll
        for (int o = 16; o; o >>= 1) a += __shfl_down_sync(0xFFFFFFFFu, a, o);
        if (lane == 0) s_dred[wrp][v] = a;
    }
    __syncthreads();
    if (tid == 0) {
        double f[6] = {0, 0, 0, 0, 0, 0};
        #pragma unroll
        for (int w = 0; w < BLK / 32; w++)
            #pragma unroll
            for (int v = 0; v < 6; v++) f[v] += s_dred[w][v];
        double nv = f[2];
        double coord = 0.0, width = 0.0;
        if (nv > 0.0) {
            coord = f[0] / fmax(nv * 6.0, 1.0);
            width = f[1] / fmax(nv * 2.0, 1.0);
        }
        double bce  = f[3] * 0.6931471805599453 / ((double)B_DIM * (double)M_DIM);
        double cont = f[4] / (double)B_DIM;
        double rcn  = f[5] / ((double)B_DIM * 128.0 * 128.0);
        out[0] = (float)(coord + width + 2.0 * bce + 0.2 * cont + 0.1 * rcn);
        g_count = 0;   // reset for next graph replay
    }
}

extern "C" void kernel_launch(void* const* d_in, const int* in_sizes, int n_in,
                              void* d_out, int out_size) {
    const float* pred = (const float*)d_in[0];
    const float* tgt  = (const float*)d_in[1];
    const float* rec  = (const float*)d_in[2];
    const float* img  = (const float*)d_in[3];
    fused_kernel<<<GRID_B, BLK>>>(pred, tgt, rec, img, (float*)d_out);
}